// round 7
// baseline (speedup 1.0000x reference)
#include <cuda_runtime.h>
#include <cstdint>
#include <cstddef>

#define NENT  50000
#define NREL  16
#define NBAS  8
#define DIM   128
#define NEDGE 800000
#define KAGG  (NBAS * DIM)   // 1024

typedef unsigned long long ull;

// ---------------- scratch (static device globals; no allocation) ----------------
__device__ __align__(128) float g_agg [(size_t)NENT * NREL * DIM];   // 409.6 MB
__device__ __align__(128) float g_aggB[(size_t)NENT * NBAS * DIM];   // 204.8 MB
__device__ __align__(128) float g_h1  [(size_t)NENT * DIM];          // 25.6 MB

// ---------------- packed f32x2 helpers (sm_100+) ----------------
__device__ __forceinline__ ull pack2(float x, float y) {
    ull r; asm("mov.b64 %0, {%1, %2};" : "=l"(r) : "f"(x), "f"(y)); return r;
}
__device__ __forceinline__ void unpack2(ull v, float& x, float& y) {
    asm("mov.b64 {%0, %1}, %2;" : "=f"(x), "=f"(y) : "l"(v));
}
__device__ __forceinline__ void fma2(ull& acc, ull a, ull b) {
    asm("fma.rn.f32x2 %0, %1, %2, %0;" : "+l"(acc) : "l"(a), "l"(b));
}

// ---------------- kernel 1: zero the (dst,rel) aggregation buffer ----------------
__global__ void k_zero_agg() {
    size_t i = (size_t)blockIdx.x * blockDim.x + threadIdx.x;
    size_t total4 = (size_t)NENT * NREL * DIM / 4;   // 25.6M float4
    if (i < total4) {
        reinterpret_cast<float4*>(g_agg)[i] = make_float4(0.f, 0.f, 0.f, 0.f);
    }
}

// ---------------- kernel 2: edge scatter  agg[dst,rel] += h[src] ----------------
// One warp per edge (grid-stride). Lane l handles floats [4l, 4l+4).
// h is 25.6 MB -> L2-resident gathers; vector reductions (16B) into agg.
__global__ void k_scatter(const float* __restrict__ h,
                          const int* __restrict__ src,
                          const int* __restrict__ dst,
                          const int* __restrict__ rel) {
    int lane  = threadIdx.x & 31;
    int warp  = (blockIdx.x * blockDim.x + threadIdx.x) >> 5;
    int nwarp = (gridDim.x * blockDim.x) >> 5;
    for (int e = warp; e < NEDGE; e += nwarp) {
        int s = __ldg(src + e);
        int d = __ldg(dst + e);
        int r = __ldg(rel + e);
        float4 v = __ldg(reinterpret_cast<const float4*>(h + (size_t)s * DIM) + lane);
        float* p = g_agg + ((size_t)d * NREL + r) * DIM + lane * 4;
        asm volatile("red.global.add.v4.f32 [%0], {%1, %2, %3, %4};"
                     :: "l"(p), "f"(v.x), "f"(v.y), "f"(v.z), "f"(v.w) : "memory");
    }
}

// ---------------- kernel 3: basis contraction  aggB[n,b,:] = sum_r wcomp[r,b] * agg[n,r,:] ----
// Thread per (n, i-quad). Memory-bound (read 409.6 MB, write 204.8 MB).
__global__ void k_contract(const float* __restrict__ wcomp) {
    __shared__ float wc[NREL * NBAS];
    int t = threadIdx.x;
    if (t < NREL * NBAS) wc[t] = wcomp[t];
    __syncthreads();

    int idx = blockIdx.x * blockDim.x + t;
    if (idx >= NENT * 32) return;
    int n  = idx >> 5;
    int iq = idx & 31;

    const float4* ag = reinterpret_cast<const float4*>(g_agg) + (size_t)n * (NREL * 32);
    float4 acc[NBAS];
#pragma unroll
    for (int b = 0; b < NBAS; b++) acc[b] = make_float4(0.f, 0.f, 0.f, 0.f);

#pragma unroll
    for (int r = 0; r < NREL; r++) {
        float4 v = ag[r * 32 + iq];
#pragma unroll
        for (int b = 0; b < NBAS; b++) {
            float w = wc[r * NBAS + b];
            acc[b].x = fmaf(w, v.x, acc[b].x);
            acc[b].y = fmaf(w, v.y, acc[b].y);
            acc[b].z = fmaf(w, v.z, acc[b].z);
            acc[b].w = fmaf(w, v.w, acc[b].w);
        }
    }
    float4* op = reinterpret_cast<float4*>(g_aggB) + (size_t)n * (NBAS * 32);
#pragma unroll
    for (int b = 0; b < NBAS; b++) op[b * 32 + iq] = acc[b];
}

// ---------------- kernel 4: fused GEMM + self-loop + bias + ReLU ----------------
// out[n,o] = relu( aggB[n,:1024] @ basis[:,:,o]  +  h[n,:] @ loop_w[:,o] + bias[o] )
// CTA: 64 rows x 128 cols, 256 threads. Thread: 4 rows x 4 col-pairs (f32x2),
// col pairs at {2*cg, 2*cg+32, 2*cg+64, 2*cg+96} -> conflict-free 8B smem loads.
__device__ __forceinline__ void gemm_phase(const float* __restrict__ A, int strideA,
                                           const float* __restrict__ W, int Ktot,
                                           int row0, int t,
                                           float (&As)[64][33], float (&Ws)[32][128],
                                           ull (&acc)[4][4]) {
    const int lrow = t >> 2;            // A-load: 0..63
    const int kq   = (t & 3) * 8;       //         8 floats along k
    const int wrow = t >> 3;            // W-load: 0..31
    const int wcol = (t & 7) * 16;      //         16 floats along o
    const int cg   = t & 15;            // compute: col group
    const int r0   = (t >> 4) * 4;      //          first of 4 rows

    for (int kt = 0; kt < Ktot; kt += 32) {
        // load A tile [64 rows x 32 k] (transposed into As[row][k], pad 33)
        int gr = row0 + lrow;
        if (gr > NENT - 1) gr = NENT - 1;           // clamp (stores guarded later)
        const float4* ap = reinterpret_cast<const float4*>(A + (size_t)gr * strideA + kt + kq);
        float4 a0 = __ldg(ap);
        float4 a1 = __ldg(ap + 1);
        As[lrow][kq + 0] = a0.x; As[lrow][kq + 1] = a0.y;
        As[lrow][kq + 2] = a0.z; As[lrow][kq + 3] = a0.w;
        As[lrow][kq + 4] = a1.x; As[lrow][kq + 5] = a1.y;
        As[lrow][kq + 6] = a1.z; As[lrow][kq + 7] = a1.w;

        // load W tile [32 k x 128 o]
        const float4* wp = reinterpret_cast<const float4*>(W + (size_t)(kt + wrow) * DIM + wcol);
        float4 w0 = __ldg(wp + 0), w1 = __ldg(wp + 1), w2 = __ldg(wp + 2), w3 = __ldg(wp + 3);
        *reinterpret_cast<float4*>(&Ws[wrow][wcol + 0])  = w0;
        *reinterpret_cast<float4*>(&Ws[wrow][wcol + 4])  = w1;
        *reinterpret_cast<float4*>(&Ws[wrow][wcol + 8])  = w2;
        *reinterpret_cast<float4*>(&Ws[wrow][wcol + 12]) = w3;

        __syncthreads();

#pragma unroll
        for (int k = 0; k < 32; k++) {
            float b0 = As[r0 + 0][k];
            float b1 = As[r0 + 1][k];
            float b2 = As[r0 + 2][k];
            float b3 = As[r0 + 3][k];
            ull pa0 = pack2(b0, b0), pa1 = pack2(b1, b1);
            ull pa2 = pack2(b2, b2), pa3 = pack2(b3, b3);
            const ull* wv = reinterpret_cast<const ull*>(&Ws[k][0]);
            ull ww0 = wv[cg + 0];
            ull ww1 = wv[cg + 16];
            ull ww2 = wv[cg + 32];
            ull ww3 = wv[cg + 48];
            fma2(acc[0][0], pa0, ww0); fma2(acc[0][1], pa0, ww1);
            fma2(acc[0][2], pa0, ww2); fma2(acc[0][3], pa0, ww3);
            fma2(acc[1][0], pa1, ww0); fma2(acc[1][1], pa1, ww1);
            fma2(acc[1][2], pa1, ww2); fma2(acc[1][3], pa1, ww3);
            fma2(acc[2][0], pa2, ww0); fma2(acc[2][1], pa2, ww1);
            fma2(acc[2][2], pa2, ww2); fma2(acc[2][3], pa2, ww3);
            fma2(acc[3][0], pa3, ww0); fma2(acc[3][1], pa3, ww1);
            fma2(acc[3][2], pa3, ww2); fma2(acc[3][3], pa3, ww3);
        }
        __syncthreads();
    }
}

__global__ __launch_bounds__(256) void k_gemm(const float* __restrict__ basis,   // [1024,128]
                                              const float* __restrict__ h,       // [NENT,128]
                                              const float* __restrict__ loopw,   // [128,128]
                                              const float* __restrict__ bias,    // [128]
                                              float* __restrict__ out) {         // [NENT,128]
    __shared__ __align__(16) float As[64][33];
    __shared__ __align__(16) float Ws[32][128];
    int t = threadIdx.x;
    int row0 = blockIdx.x * 64;

    ull acc[4][4];
#pragma unroll
    for (int j = 0; j < 4; j++)
#pragma unroll
        for (int p = 0; p < 4; p++) acc[j][p] = 0ULL;   // two packed +0.0f

    gemm_phase(g_aggB, KAGG, basis, KAGG, row0, t, As, Ws, acc);  // message term
    gemm_phase(h,      DIM,  loopw, DIM,  row0, t, As, Ws, acc);  // self-loop term

    // epilogue: + bias, ReLU, store (8B per pair, pairs at 2*cg + 32*p)
    const int cg = t & 15;
    const int r0 = (t >> 4) * 4;
    float2 bb[4];
#pragma unroll
    for (int p = 0; p < 4; p++)
        bb[p] = __ldg(reinterpret_cast<const float2*>(bias) + (16 * p + cg));

#pragma unroll
    for (int j = 0; j < 4; j++) {
        int gr = row0 + r0 + j;
        if (gr < NENT) {
#pragma unroll
            for (int p = 0; p < 4; p++) {
                float x, y;
                unpack2(acc[j][p], x, y);
                x = fmaxf(x + bb[p].x, 0.f);
                y = fmaxf(y + bb[p].y, 0.f);
                *reinterpret_cast<float2*>(out + (size_t)gr * DIM + 32 * p + 2 * cg) =
                    make_float2(x, y);
            }
        }
    }
}

// ---------------- launcher ----------------
extern "C" void kernel_launch(void* const* d_in, const int* in_sizes, int n_in,
                              void* d_out, int out_size) {
    const float* emb    = (const float*)d_in[0];
    const float* basis1 = (const float*)d_in[1];
    const float* wcomp1 = (const float*)d_in[2];
    const float* loopw1 = (const float*)d_in[3];
    const float* bias1  = (const float*)d_in[4];
    const float* basis2 = (const float*)d_in[5];
    const float* wcomp2 = (const float*)d_in[6];
    const float* loopw2 = (const float*)d_in[7];
    const float* bias2  = (const float*)d_in[8];
    const int*   src    = (const int*)d_in[9];
    const int*   dst    = (const int*)d_in[10];
    const int*   rel    = (const int*)d_in[11];
    float*       out    = (float*)d_out;

    void* h1p_ = nullptr;
    cudaGetSymbolAddress(&h1p_, g_h1);      // query only; no allocation
    float* h1p = (float*)h1p_;

    const int ZB = (int)(((size_t)NENT * NREL * DIM / 4 + 255) / 256);  // 100000
    const int CB = (NENT * 32 + 255) / 256;                             // 6250
    const int GB = (NENT + 63) / 64;                                    // 782

    // ---- layer 1 ----
    k_zero_agg<<<ZB, 256>>>();
    k_scatter<<<2048, 256>>>(emb, src, dst, rel);
    k_contract<<<CB, 256>>>(wcomp1);
    k_gemm<<<GB, 256>>>(basis1, emb, loopw1, bias1, h1p);

    // ---- layer 2 ----
    k_zero_agg<<<ZB, 256>>>();
    k_scatter<<<2048, 256>>>(h1p, src, dst, rel);
    k_contract<<<CB, 256>>>(wcomp2);
    k_gemm<<<GB, 256>>>(basis2, h1p, loopw2, bias2, out);
}

// round 8
// speedup vs baseline: 1.0075x; 1.0075x over previous
#include <cuda_runtime.h>
#include <cstdint>
#include <cstddef>

#define NENT  50000
#define NREL  16
#define NBAS  8
#define DIM   128
#define NEDGE 800000
#define KAGG  (NBAS * DIM)   // 1024

typedef unsigned long long ull;

// ---------------- scratch (static device globals; no allocation) ----------------
__device__ __align__(128) float g_agg [(size_t)NENT * NREL * DIM];   // 409.6 MB
__device__ __align__(128) float g_aggB[(size_t)NENT * NBAS * DIM];   // 204.8 MB
__device__ __align__(128) float g_h1  [(size_t)NENT * DIM];          // 25.6 MB

// ---------------- packed f32x2 helpers (sm_100+) ----------------
__device__ __forceinline__ void unpack2(ull v, float& x, float& y) {
    asm("mov.b64 {%0, %1}, %2;" : "=f"(x), "=f"(y) : "l"(v));
}
__device__ __forceinline__ void fma2(ull& acc, ull a, ull b) {
    asm("fma.rn.f32x2 %0, %1, %2, %0;" : "+l"(acc) : "l"(a), "l"(b));
}

// ---------------- kernel 2: edge scatter  agg[dst,rel] += h[src] ----------------
// One warp per edge (grid-stride). Lane l handles floats [4l, 4l+4).
// h is 25.6 MB -> L2-resident gathers; vector reductions (16B) into agg.
__global__ void k_scatter(const float* __restrict__ h,
                          const int* __restrict__ src,
                          const int* __restrict__ dst,
                          const int* __restrict__ rel) {
    int lane  = threadIdx.x & 31;
    int warp  = (blockIdx.x * blockDim.x + threadIdx.x) >> 5;
    int nwarp = (gridDim.x * blockDim.x) >> 5;
    for (int e = warp; e < NEDGE; e += nwarp) {
        int s = __ldg(src + e);
        int d = __ldg(dst + e);
        int r = __ldg(rel + e);
        float4 v = __ldg(reinterpret_cast<const float4*>(h + (size_t)s * DIM) + lane);
        float* p = g_agg + ((size_t)d * NREL + r) * DIM + lane * 4;
        asm volatile("red.global.add.v4.f32 [%0], {%1, %2, %3, %4};"
                     :: "l"(p), "f"(v.x), "f"(v.y), "f"(v.z), "f"(v.w) : "memory");
    }
}

// ---------------- kernel 3: basis contraction  aggB[n,b,:] = sum_r wcomp[r,b] * agg[n,r,:] ----
__global__ void k_contract(const float* __restrict__ wcomp) {
    __shared__ float wc[NREL * NBAS];
    int t = threadIdx.x;
    if (t < NREL * NBAS) wc[t] = wcomp[t];
    __syncthreads();

    int idx = blockIdx.x * blockDim.x + t;
    if (idx >= NENT * 32) return;
    int n  = idx >> 5;
    int iq = idx & 31;

    const float4* ag = reinterpret_cast<const float4*>(g_agg) + (size_t)n * (NREL * 32);
    float4 acc[NBAS];
#pragma unroll
    for (int b = 0; b < NBAS; b++) acc[b] = make_float4(0.f, 0.f, 0.f, 0.f);

#pragma unroll
    for (int r = 0; r < NREL; r++) {
        float4 v = ag[r * 32 + iq];
#pragma unroll
        for (int b = 0; b < NBAS; b++) {
            float w = wc[r * NBAS + b];
            acc[b].x = fmaf(w, v.x, acc[b].x);
            acc[b].y = fmaf(w, v.y, acc[b].y);
            acc[b].z = fmaf(w, v.z, acc[b].z);
            acc[b].w = fmaf(w, v.w, acc[b].w);
        }
    }
    float4* op = reinterpret_cast<float4*>(g_aggB) + (size_t)n * (NBAS * 32);
#pragma unroll
    for (int b = 0; b < NBAS; b++) op[b * 32 + iq] = acc[b];
}

// ---------------- kernel 4: fused GEMM + self-loop + bias + ReLU ----------------
// out[n,o] = relu( aggB[n,:1024] @ basis  +  h[n,:] @ loop_w + bias )
// CTA: 32 rows x 128 cols, 128 threads, occ 6. Thread: 4 rows x 4 col-pairs.
// A is staged in smem as DUPLICATED float2 pairs {v,v} so a 16B LDS yields two
// ready f32x2 broadcast operands (k, k+1) -> no mov.b64 packs, 1 crossbar
// phase per As load. Ws 8B loads hit 16 distinct banks (conflict-free).
#define TR 32            // rows per CTA tile
#define KT 32            // k per tile

__device__ __forceinline__ void gemm_phase(const float* __restrict__ A, int strideA,
                                           const float* __restrict__ W, int Ktot,
                                           int row0, int t,
                                           float2 (&As2)[TR][KT + 2],
                                           float  (&Ws)[KT][128],
                                           ull (&acc)[4][4]) {
    const int cg = t & 15;            // compute: col group (cols 2*cg + 32*p)
    const int rg = t >> 4;            // compute: row group (rows rg*4 + j)

    for (int kt = 0; kt < Ktot; kt += KT) {
        // fill A tile: 32 rows x 32 k = 256 float4, 2 per thread; duplicate pairs
#pragma unroll
        for (int i = 0; i < 2; i++) {
            int f   = t + 128 * i;
            int row = f >> 3;
            int kq  = (f & 7) * 4;
            int gr  = row0 + row;
            if (gr > NENT - 1) gr = NENT - 1;        // clamp (stores guarded later)
            float4 v = __ldg(reinterpret_cast<const float4*>(
                                 A + (size_t)gr * strideA + kt + kq));
            *reinterpret_cast<float4*>(&As2[row][kq])     = make_float4(v.x, v.x, v.y, v.y);
            *reinterpret_cast<float4*>(&As2[row][kq + 2]) = make_float4(v.z, v.z, v.w, v.w);
        }
        // fill W tile: 32 k x 128 o = 1024 float4, 8 per thread
#pragma unroll
        for (int i = 0; i < 8; i++) {
            int f  = t + 128 * i;
            int wr = f >> 5;
            int wc = (f & 31) * 4;
            float4 w = __ldg(reinterpret_cast<const float4*>(
                                 W + (size_t)(kt + wr) * DIM + wc));
            *reinterpret_cast<float4*>(&Ws[wr][wc]) = w;
        }
        __syncthreads();

#pragma unroll
        for (int k2 = 0; k2 < KT / 2; k2++) {
            // a[j] = ({v_k,v_k}, {v_k1,v_k1}) for row rg*4+j
            ulonglong2 a[4];
#pragma unroll
            for (int j = 0; j < 4; j++)
                a[j] = *reinterpret_cast<const ulonglong2*>(&As2[rg * 4 + j][k2 * 2]);
#pragma unroll
            for (int kk = 0; kk < 2; kk++) {
                int k = k2 * 2 + kk;
                const ull* wv = reinterpret_cast<const ull*>(&Ws[k][0]);
                ull w0 = wv[cg + 0];
                ull w1 = wv[cg + 16];
                ull w2 = wv[cg + 32];
                ull w3 = wv[cg + 48];
#pragma unroll
                for (int j = 0; j < 4; j++) {
                    ull pa = kk ? a[j].y : a[j].x;
                    fma2(acc[j][0], pa, w0);
                    fma2(acc[j][1], pa, w1);
                    fma2(acc[j][2], pa, w2);
                    fma2(acc[j][3], pa, w3);
                }
            }
        }
        __syncthreads();
    }
}

__global__ __launch_bounds__(128, 6)
void k_gemm(const float* __restrict__ basis,   // [1024,128]
            const float* __restrict__ h,       // [NENT,128]
            const float* __restrict__ loopw,   // [128,128]
            const float* __restrict__ bias,    // [128]
            float* __restrict__ out) {         // [NENT,128]
    __shared__ __align__(16) float2 As2[TR][KT + 2];
    __shared__ __align__(16) float  Ws [KT][128];
    int t = threadIdx.x;
    int row0 = blockIdx.x * TR;

    ull acc[4][4];
#pragma unroll
    for (int j = 0; j < 4; j++)
#pragma unroll
        for (int p = 0; p < 4; p++) acc[j][p] = 0ULL;   // two packed +0.0f

    gemm_phase(g_aggB, KAGG, basis, KAGG, row0, t, As2, Ws, acc);  // message term
    gemm_phase(h,      DIM,  loopw, DIM,  row0, t, As2, Ws, acc);  // self-loop term

    // epilogue: + bias, ReLU, store (8B per pair, pairs at 2*cg + 32*p)
    const int cg = t & 15;
    const int rg = t >> 4;
    float2 bb[4];
#pragma unroll
    for (int p = 0; p < 4; p++)
        bb[p] = __ldg(reinterpret_cast<const float2*>(bias) + (16 * p + cg));

#pragma unroll
    for (int j = 0; j < 4; j++) {
        int gr = row0 + rg * 4 + j;
        if (gr < NENT) {
#pragma unroll
            for (int p = 0; p < 4; p++) {
                float x, y;
                unpack2(acc[j][p], x, y);
                x = fmaxf(x + bb[p].x, 0.f);
                y = fmaxf(y + bb[p].y, 0.f);
                *reinterpret_cast<float2*>(out + (size_t)gr * DIM + 32 * p + 2 * cg) =
                    make_float2(x, y);
            }
        }
    }
}

// ---------------- launcher ----------------
extern "C" void kernel_launch(void* const* d_in, const int* in_sizes, int n_in,
                              void* d_out, int out_size) {
    const float* emb    = (const float*)d_in[0];
    const float* basis1 = (const float*)d_in[1];
    const float* wcomp1 = (const float*)d_in[2];
    const float* loopw1 = (const float*)d_in[3];
    const float* bias1  = (const float*)d_in[4];
    const float* basis2 = (const float*)d_in[5];
    const float* wcomp2 = (const float*)d_in[6];
    const float* loopw2 = (const float*)d_in[7];
    const float* bias2  = (const float*)d_in[8];
    const int*   src    = (const int*)d_in[9];
    const int*   dst    = (const int*)d_in[10];
    const int*   rel    = (const int*)d_in[11];
    float*       out    = (float*)d_out;

    void* h1p_ = nullptr;
    cudaGetSymbolAddress(&h1p_, g_h1);      // query only; no allocation
    float* h1p = (float*)h1p_;
    void* aggp_ = nullptr;
    cudaGetSymbolAddress(&aggp_, g_agg);
    const size_t agg_bytes = (size_t)NENT * NREL * DIM * sizeof(float);

    const int CB = (NENT * 32 + 255) / 256;   // 6250
    const int GB = (NENT + TR - 1) / TR;      // 1563

    // ---- layer 1 ----
    cudaMemsetAsync(aggp_, 0, agg_bytes);
    k_scatter<<<2048, 256>>>(emb, src, dst, rel);
    k_contract<<<CB, 256>>>(wcomp1);
    k_gemm<<<GB, 128>>>(basis1, emb, loopw1, bias1, h1p);

    // ---- layer 2 ----
    cudaMemsetAsync(aggp_, 0, agg_bytes);
    k_scatter<<<2048, 256>>>(h1p, src, dst, rel);
    k_contract<<<CB, 256>>>(wcomp2);
    k_gemm<<<GB, 128>>>(basis2, h1p, loopw2, bias2, out);
}

// round 12
// speedup vs baseline: 1.5874x; 1.5756x over previous
#include <cuda_runtime.h>
#include <cuda_bf16.h>
#include <cstdint>
#include <cstddef>

#define NENT  50000
#define NREL  16
#define NBAS  8
#define DIM   128
#define NEDGE 800000
#define KAGG  (NBAS * DIM)     // 1024
#define KTOT  (KAGG + DIM)     // 1152 = aggB(1024) ‖ h(128)
#define KC    64               // k per GEMM chunk
#define NCH   (KTOT / KC)      // 18
#define GM    128              // rows per CTA tile
#define ASTR_B 144             // smem row stride bytes (128B data + 16B pad -> conflict-free ldmatrix)
#define TILE_B (128 * ASTR_B)  // 18432 bytes per smem plane

typedef unsigned long long ull;

// ---------------- scratch (static device globals; no allocation) ----------------
__device__ __align__(128) float g_agg[(size_t)NENT * NREL * DIM];            // 409.6 MB
__device__ __align__(128) float g_h1 [(size_t)NENT * DIM];                   // 25.6 MB
// A = [aggB | h] as bf16 hi/lo planes, [NENT][KTOT]
__device__ __align__(128) __nv_bfloat16 g_Ah[(size_t)NENT * KTOT];           // 115.2 MB
__device__ __align__(128) __nv_bfloat16 g_Al[(size_t)NENT * KTOT];           // 115.2 MB
// W = [basis | loop_w] as bf16 hi/lo planes, [n=128][k=KTOT]
__device__ __align__(128) __nv_bfloat16 g_Wh[(size_t)128 * KTOT];
__device__ __align__(128) __nv_bfloat16 g_Wl[(size_t)128 * KTOT];

// ---------------- helpers ----------------
__device__ __forceinline__ uint32_t smem_u32(const void* p) {
    uint32_t a;
    asm("{ .reg .u64 t; cvta.to.shared.u64 t, %1; cvt.u32.u64 %0, t; }" : "=r"(a) : "l"(p));
    return a;
}
__device__ __forceinline__ uint32_t bf2_bits(__nv_bfloat16 a, __nv_bfloat16 b) {
    __nv_bfloat162 t = __halves2bfloat162(a, b);   // a -> low 16 bits
    return *reinterpret_cast<uint32_t*>(&t);
}
__device__ __forceinline__ uint2 split4(float4 v, uint2& lo) {
    __nv_bfloat16 h0 = __float2bfloat16(v.x);
    __nv_bfloat16 h1 = __float2bfloat16(v.y);
    __nv_bfloat16 h2 = __float2bfloat16(v.z);
    __nv_bfloat16 h3 = __float2bfloat16(v.w);
    lo = make_uint2(bf2_bits(__float2bfloat16(v.x - __bfloat162float(h0)),
                             __float2bfloat16(v.y - __bfloat162float(h1))),
                    bf2_bits(__float2bfloat16(v.z - __bfloat162float(h2)),
                             __float2bfloat16(v.w - __bfloat162float(h3))));
    return make_uint2(bf2_bits(h0, h1), bf2_bits(h2, h3));
}
__device__ __forceinline__ void ldsm4(uint32_t* r, uint32_t addr) {
    asm volatile("ldmatrix.sync.aligned.m8n8.x4.shared.b16 {%0,%1,%2,%3}, [%4];"
                 : "=r"(r[0]), "=r"(r[1]), "=r"(r[2]), "=r"(r[3]) : "r"(addr));
}
__device__ __forceinline__ void mma16816(float* d, const uint32_t* a, const uint32_t* b) {
    asm volatile(
        "mma.sync.aligned.m16n8k16.row.col.f32.bf16.bf16.f32 "
        "{%0,%1,%2,%3}, {%4,%5,%6,%7}, {%8,%9}, {%0,%1,%2,%3};"
        : "+f"(d[0]), "+f"(d[1]), "+f"(d[2]), "+f"(d[3])
        : "r"(a[0]), "r"(a[1]), "r"(a[2]), "r"(a[3]), "r"(b[0]), "r"(b[1]));
}

// ---------------- kernel: edge scatter  agg[dst,rel] += h[src] ----------------
__global__ void k_scatter(const float* __restrict__ h,
                          const int* __restrict__ src,
                          const int* __restrict__ dst,
                          const int* __restrict__ rel) {
    int lane  = threadIdx.x & 31;
    int warp  = (blockIdx.x * blockDim.x + threadIdx.x) >> 5;
    int nwarp = (gridDim.x * blockDim.x) >> 5;
    for (int e = warp; e < NEDGE; e += nwarp) {
        int s = __ldg(src + e);
        int d = __ldg(dst + e);
        int r = __ldg(rel + e);
        float4 v = __ldg(reinterpret_cast<const float4*>(h + (size_t)s * DIM) + lane);
        float* p = g_agg + ((size_t)d * NREL + r) * DIM + lane * 4;
        asm volatile("red.global.add.v4.f32 [%0], {%1, %2, %3, %4};"
                     :: "l"(p), "f"(v.x), "f"(v.y), "f"(v.z), "f"(v.w) : "memory");
    }
}

// ---------------- kernel: contraction + bf16 hi/lo split ----------------
// g_A{h,l}[n][b*128 + i] = split( sum_r wcomp[r,b] * agg[n,r,i] )
__global__ void k_contract(const float* __restrict__ wcomp) {
    __shared__ float wc[NREL * NBAS];
    int t = threadIdx.x;
    if (t < NREL * NBAS) wc[t] = wcomp[t];
    __syncthreads();

    int idx = blockIdx.x * blockDim.x + t;
    if (idx >= NENT * 32) return;
    int n  = idx >> 5;
    int iq = idx & 31;

    const float4* ag = reinterpret_cast<const float4*>(g_agg) + (size_t)n * (NREL * 32);
    float4 acc[NBAS];
#pragma unroll
    for (int b = 0; b < NBAS; b++) acc[b] = make_float4(0.f, 0.f, 0.f, 0.f);
#pragma unroll
    for (int r = 0; r < NREL; r++) {
        float4 v = ag[r * 32 + iq];
#pragma unroll
        for (int b = 0; b < NBAS; b++) {
            float w = wc[r * NBAS + b];
            acc[b].x = fmaf(w, v.x, acc[b].x);
            acc[b].y = fmaf(w, v.y, acc[b].y);
            acc[b].z = fmaf(w, v.z, acc[b].z);
            acc[b].w = fmaf(w, v.w, acc[b].w);
        }
    }
#pragma unroll
    for (int b = 0; b < NBAS; b++) {
        uint2 lo;
        uint2 hi = split4(acc[b], lo);
        size_t off = (size_t)n * KTOT + b * DIM + iq * 4;
        *reinterpret_cast<uint2*>(g_Ah + off) = hi;
        *reinterpret_cast<uint2*>(g_Al + off) = lo;
    }
}

// ---------------- kernel: self-loop input -> A plane cols 1024..1151 ----------------
__global__ void k_convert_h(const float* __restrict__ h) {
    int gid = blockIdx.x * blockDim.x + threadIdx.x;
    if (gid >= NENT * 32) return;
    int n  = gid >> 5;
    int jq = (gid & 31) * 4;
    float4 v = __ldg(reinterpret_cast<const float4*>(h + (size_t)n * DIM + jq));
    uint2 lo;
    uint2 hi = split4(v, lo);
    size_t off = (size_t)n * KTOT + KAGG + jq;
    *reinterpret_cast<uint2*>(g_Ah + off) = hi;
    *reinterpret_cast<uint2*>(g_Al + off) = lo;
}

// ---------------- kernel: W -> bf16 hi/lo planes, [n][k] ----------------
__global__ void k_convert_w(const float* __restrict__ basis,
                            const float* __restrict__ loopw) {
    int gid = blockIdx.x * blockDim.x + threadIdx.x;
    if (gid >= 128 * KTOT) return;
    int n = gid / KTOT;
    int k = gid % KTOT;
    float v = (k < KAGG) ? __ldg(basis + (size_t)k * DIM + n)
                         : __ldg(loopw + (size_t)(k - KAGG) * DIM + n);
    __nv_bfloat16 hi = __float2bfloat16(v);
    g_Wh[gid] = hi;
    g_Wl[gid] = __float2bfloat16(v - __bfloat162float(hi));
}

// ---------------- kernel: tensor-core GEMM (mma.sync bf16, hi/lo split) ----------------
// out[m,:] = relu( A[m,:1152] @ W + bias ),  A = Ah+Al, W = Wh+Wl,
// computed as Ah·Wh + Al·Wh + Ah·Wl with fp32 accumulation.
// CTA: 256 thr (8 warps, 4M x 2N), tile 128x128; warp tile 32x64; K chunk 64.
__global__ __launch_bounds__(256, 2)
void k_gemm_tc(const float* __restrict__ bias, float* __restrict__ out) {
    extern __shared__ char sm[];
    char* pAh = sm;
    char* pAl = sm + TILE_B;
    char* pWh = sm + 2 * TILE_B;
    char* pWl = sm + 3 * TILE_B;
    const uint32_t uAh = smem_u32(pAh);
    const uint32_t uAl = smem_u32(pAl);
    const uint32_t uWh = smem_u32(pWh);
    const uint32_t uWl = smem_u32(pWl);

    const int t    = threadIdx.x;
    const int l    = t & 31;
    const int w    = t >> 5;
    const int mw   = w >> 1;          // 0..3
    const int nw   = w & 1;           // 0..1
    const int grp  = l >> 2;
    const int tig  = l & 3;
    const int sub  = l >> 3;
    const int lr   = l & 7;
    const int row0 = blockIdx.x * GM;

    // ldmatrix lane geometry (A tiles ordered a0,a1,a2,a3; W pairs b0/b1 per ntile)
    const uint32_t aOff = (uint32_t)((mw * 32 + lr + (sub & 1) * 8) * ASTR_B + ((sub >> 1) * 16));
    const uint32_t wOff = (uint32_t)((nw * 64 + lr + (sub >> 1) * 8) * ASTR_B + ((sub & 1) * 16));

    float d[2][8][4];
#pragma unroll
    for (int mt = 0; mt < 2; mt++)
#pragma unroll
        for (int nt = 0; nt < 8; nt++)
#pragma unroll
            for (int e = 0; e < 4; e++) d[mt][nt][e] = 0.f;

    for (int c = 0; c < NCH; c++) {
        const int k0 = c * KC;
        // ---- stage: A hi/lo + W hi/lo, 128x64 bf16 each, padded stride ----
#pragma unroll
        for (int i = 0; i < 4; i++) {
            int idx = t + 256 * i;           // 0..1023 (16B units)
            int n   = idx >> 3;
            int u   = idx & 7;
            int gr  = row0 + n;
            if (gr > NENT - 1) gr = NENT - 1;               // clamp; stores guarded later
            size_t ga = (size_t)gr * KTOT + k0 + u * 8;
            size_t gw = (size_t)n * KTOT + k0 + u * 8;
            uint4 vh = __ldg(reinterpret_cast<const uint4*>(g_Ah + ga));
            uint4 vl = __ldg(reinterpret_cast<const uint4*>(g_Al + ga));
            uint4 wh = __ldg(reinterpret_cast<const uint4*>(g_Wh + gw));
            uint4 wl = __ldg(reinterpret_cast<const uint4*>(g_Wl + gw));
            int so = n * ASTR_B + u * 16;
            *reinterpret_cast<uint4*>(pAh + so) = vh;
            *reinterpret_cast<uint4*>(pAl + so) = vl;
            *reinterpret_cast<uint4*>(pWh + so) = wh;
            *reinterpret_cast<uint4*>(pWl + so) = wl;
        }
        __syncthreads();

        // ---- compute: 4 k16 steps x 3 products ----
#pragma unroll
        for (int ks = 0; ks < 4; ks++) {
            const uint32_t kb = (uint32_t)(ks * 32);
            uint32_t A[2][4], A2[2][4], W[4][4];
            ldsm4(A[0], uAh + aOff + kb);
            ldsm4(A[1], uAh + aOff + kb + 16 * ASTR_B);
#pragma unroll
            for (int j = 0; j < 4; j++) ldsm4(W[j], uWh + wOff + kb + j * 16 * ASTR_B);
            // Ah * Wh
#pragma unroll
            for (int mt = 0; mt < 2; mt++)
#pragma unroll
                for (int j = 0; j < 4; j++) {
                    mma16816(d[mt][2 * j],     A[mt], &W[j][0]);
                    mma16816(d[mt][2 * j + 1], A[mt], &W[j][2]);
                }
            // Al * Wh
            ldsm4(A2[0], uAl + aOff + kb);
            ldsm4(A2[1], uAl + aOff + kb + 16 * ASTR_B);
#pragma unroll
            for (int mt = 0; mt < 2; mt++)
#pragma unroll
                for (int j = 0; j < 4; j++) {
                    mma16816(d[mt][2 * j],     A2[mt], &W[j][0]);
                    mma16816(d[mt][2 * j + 1], A2[mt], &W[j][2]);
                }
            // Ah * Wl (reuse W regs)
#pragma unroll
            for (int j = 0; j < 4; j++) ldsm4(W[j], uWl + wOff + kb + j * 16 * ASTR_B);
#pragma unroll
            for (int mt = 0; mt < 2; mt++)
#pragma unroll
                for (int j = 0; j < 4; j++) {
                    mma16816(d[mt][2 * j],     A[mt], &W[j][0]);
                    mma16816(d[mt][2 * j + 1], A[mt], &W[j][2]);
                }
        }
        __syncthreads();
    }

    // ---- epilogue: bias + ReLU, fp32 stores ----
    const int rbase = row0 + mw * 32 + grp;
#pragma unroll
    for (int mt = 0; mt < 2; mt++) {
        int rA = rbase + mt * 16;
        int rB = rA + 8;
#pragma unroll
        for (int nt = 0; nt < 8; nt++) {
            int cc = nw * 64 + nt * 8 + tig * 2;
            float2 bb = __ldg(reinterpret_cast<const float2*>(bias + cc));
            if (rA < NENT) {
                float2 o;
                o.x = fmaxf(d[mt][nt][0] + bb.x, 0.f);
                o.y = fmaxf(d[mt][nt][1] + bb.y, 0.f);
                *reinterpret_cast<float2*>(out + (size_t)rA * DIM + cc) = o;
            }
            if (rB < NENT) {
                float2 o;
                o.x = fmaxf(d[mt][nt][2] + bb.x, 0.f);
                o.y = fmaxf(d[mt][nt][3] + bb.y, 0.f);
                *reinterpret_cast<float2*>(out + (size_t)rB * DIM + cc) = o;
            }
        }
    }
}

// ---------------- launcher ----------------
extern "C" void kernel_launch(void* const* d_in, const int* in_sizes, int n_in,
                              void* d_out, int out_size) {
    const float* emb    = (const float*)d_in[0];
    const float* basis1 = (const float*)d_in[1];
    const float* wcomp1 = (const float*)d_in[2];
    const float* loopw1 = (const float*)d_in[3];
    const float* bias1  = (const float*)d_in[4];
    const float* basis2 = (const float*)d_in[5];
    const float* wcomp2 = (const float*)d_in[6];
    const float* loopw2 = (const float*)d_in[7];
    const float* bias2  = (const float*)d_in[8];
    const int*   src    = (const int*)d_in[9];
    const int*   dst    = (const int*)d_in[10];
    const int*   rel    = (const int*)d_in[11];
    float*       out    = (float*)d_out;

    void* h1p_ = nullptr;
    cudaGetSymbolAddress(&h1p_, g_h1);      // address query only; no allocation
    float* h1p = (float*)h1p_;
    void* aggp_ = nullptr;
    cudaGetSymbolAddress(&aggp_, g_agg);
    const size_t agg_bytes = (size_t)NENT * NREL * DIM * sizeof(float);

    const int CB = (NENT * 32 + 255) / 256;          // contract/convert_h blocks
    const int GB = (NENT + GM - 1) / GM;             // 391
    const int WB = (128 * KTOT + 255) / 256;         // 576
    const int SMEM_GEMM = 4 * TILE_B;                // 73728

    cudaFuncSetAttribute(k_gemm_tc, cudaFuncAttributeMaxDynamicSharedMemorySize, SMEM_GEMM);

    // ---- layer 1 ----
    cudaMemsetAsync(aggp_, 0, agg_bytes);
    k_scatter<<<2048, 256>>>(emb, src, dst, rel);
    k_contract<<<CB, 256>>>(wcomp1);
    k_convert_h<<<CB, 256>>>(emb);
    k_convert_w<<<WB, 256>>>(basis1, loopw1);
    k_gemm_tc<<<GB, 256, SMEM_GEMM>>>(bias1, h1p);

    // ---- layer 2 ----
    cudaMemsetAsync(aggp_, 0, agg_bytes);
    k_scatter<<<2048, 256>>>(h1p, src, dst, rel);
    k_contract<<<CB, 256>>>(wcomp2);
    k_convert_h<<<CB, 256>>>(h1p);
    k_convert_w<<<WB, 256>>>(basis2, loopw2);
    k_gemm_tc<<<GB, 256, SMEM_GEMM>>>(bias2, out);
}